// round 1
// baseline (speedup 1.0000x reference)
#include <cuda_runtime.h>
#include <cuda_bf16.h>

#define NN   20000
#define EE   320000
#define DD   300
#define LL   5
#define VV   119
#define EDIMM 7
#define GG   128
#define NCC  6
#define HH   150
#define BN_EPS 1e-5f

// ---------------- scratch (static device memory; no runtime allocs) ----------
__device__ float g_h[NN * DD];
__device__ float g_bufA[NN * DD];
__device__ float g_bufB[NN * DD];
__device__ int   g_rowptr[NN + 1];
__device__ int   g_fill[NN];
__device__ int   g_csrc[EE];
__device__ int   g_ceid[EE];
__device__ float g_sum[DD];
__device__ float g_sumsq[DD];
__device__ float g_pool[GG * DD];
__device__ float g_cnt[GG];

// ---------------- CSR build --------------------------------------------------
__global__ void k_zero_csr() {
    int i = blockIdx.x * blockDim.x + threadIdx.x;
    if (i <= NN) g_rowptr[i] = 0;
}

__global__ void k_hist(const int* __restrict__ ei) {
    int e = blockIdx.x * blockDim.x + threadIdx.x;
    if (e < EE) {
        int dst = ei[EE + e];
        atomicAdd(&g_rowptr[dst + 1], 1);
    }
}

__global__ void k_scan() {
    // inclusive scan over g_rowptr[0..NN]  (20001 entries), 1 block of 1024
    __shared__ int s[1024];
    const int CH = 20;  // 1024*20 = 20480 >= 20001
    int t = threadIdx.x;
    int base = t * CH;
    int vals[CH];
    int run = 0;
#pragma unroll
    for (int i = 0; i < CH; i++) {
        int idx = base + i;
        int v = (idx <= NN) ? g_rowptr[idx] : 0;
        run += v;
        vals[i] = run;
    }
    s[t] = run;
    __syncthreads();
    for (int off = 1; off < 1024; off <<= 1) {
        int v = (t >= off) ? s[t - off] : 0;
        __syncthreads();
        s[t] += v;
        __syncthreads();
    }
    int pre = s[t] - run;
#pragma unroll
    for (int i = 0; i < CH; i++) {
        int idx = base + i;
        if (idx <= NN) g_rowptr[idx] = pre + vals[i];
    }
}

__global__ void k_fill() {
    int i = blockIdx.x * blockDim.x + threadIdx.x;
    if (i < NN) g_fill[i] = g_rowptr[i];
}

__global__ void k_scatter(const int* __restrict__ ei) {
    int e = blockIdx.x * blockDim.x + threadIdx.x;
    if (e < EE) {
        int src = ei[e];
        int dst = ei[EE + e];
        int pos = atomicAdd(&g_fill[dst], 1);
        g_csrc[pos] = src;
        g_ceid[pos] = e;
    }
}

// ---------------- node encoder ----------------------------------------------
__global__ void k_encode(const int* __restrict__ x, const float* __restrict__ emb) {
    int idx = blockIdx.x * blockDim.x + threadIdx.x;
    if (idx < NN * DD) {
        int n = idx / DD;
        int d = idx - n * DD;
        g_h[idx] = emb[x[n] * DD + d];
    }
}

// ---------------- GINE aggregation: warp per node, edge MLP recomputed -------
__global__ void __launch_bounds__(128) k_aggregate(
    const float* __restrict__ edge_attr,
    const float* __restrict__ edge_W,
    const float* __restrict__ edge_b,
    const float* __restrict__ eps, int layer,
    float* __restrict__ zout)
{
    int tid = threadIdx.x;
    int warp = tid >> 5, lane = tid & 31;
    int node = blockIdx.x * 4 + warp;
    if (node >= NN) return;

    // per-lane slice of the edge-encoder weights (constant across edges)
    float wreg[10][EDIMM];
    float ebr[10];
#pragma unroll
    for (int j = 0; j < 10; j++) {
        int d = lane + 32 * j;
        if (d < DD) {
            ebr[j] = edge_b[d];
#pragma unroll
            for (int k = 0; k < EDIMM; k++) wreg[j][k] = edge_W[k * DD + d];
        } else {
            ebr[j] = 0.f;
#pragma unroll
            for (int k = 0; k < EDIMM; k++) wreg[j][k] = 0.f;
        }
    }

    float acc[10];
#pragma unroll
    for (int j = 0; j < 10; j++) acc[j] = 0.f;

    int beg = g_rowptr[node], end = g_rowptr[node + 1];
    for (int idx = beg; idx < end; idx++) {
        int src = g_csrc[idx];
        int eid = g_ceid[idx];
        float a[EDIMM];
#pragma unroll
        for (int k = 0; k < EDIMM; k++) a[k] = edge_attr[eid * EDIMM + k];
        const float* hrow = g_h + src * DD;
#pragma unroll
        for (int j = 0; j < 10; j++) {
            int d = lane + 32 * j;
            if (d < DD) {
                float ea = ebr[j];
#pragma unroll
                for (int k = 0; k < EDIMM; k++) ea = fmaf(a[k], wreg[j][k], ea);
                float v = hrow[d] + ea;
                acc[j] += fmaxf(v, 0.f);
            }
        }
    }

    float epsv = 1.f + eps[layer];
#pragma unroll
    for (int j = 0; j < 10; j++) {
        int d = lane + 32 * j;
        if (d < DD) zout[node * DD + d] = epsv * g_h[node * DD + d] + acc[j];
    }
}

// ---------------- fp32 tiled GEMM + bias: C[M,300] = A[M,300] @ B[300,300] ---
#define BM 128
#define BN 128
#define BK 8
__global__ void __launch_bounds__(256) k_gemm_bias(
    const float* __restrict__ A, const float* __restrict__ B,
    const float* __restrict__ bias, float* __restrict__ C, int M)
{
    __shared__ float As[BK][BM];
    __shared__ float Bs[BK][BN];
    int tid = threadIdx.x;
    int m0 = blockIdx.y * BM;
    int n0 = blockIdx.x * BN;
    int tx = tid & 15, ty = tid >> 4;

    float acc[8][8];
#pragma unroll
    for (int i = 0; i < 8; i++)
#pragma unroll
        for (int j = 0; j < 8; j++) acc[i][j] = 0.f;

    int arow = tid >> 1;          // 0..127
    int acol = (tid & 1) * 4;     // 0 or 4
    int brow = tid >> 5;          // 0..7
    int bcol = (tid & 31) * 4;    // 0..124

    for (int k0 = 0; k0 < DD; k0 += BK) {
#pragma unroll
        for (int q = 0; q < 4; q++) {
            int k = k0 + acol + q;
            int m = m0 + arow;
            As[acol + q][arow] = (m < M && k < DD) ? A[m * DD + k] : 0.f;
        }
#pragma unroll
        for (int q = 0; q < 4; q++) {
            int k = k0 + brow;
            int n = n0 + bcol + q;
            Bs[brow][bcol + q] = (k < DD && n < DD) ? B[k * DD + n] : 0.f;
        }
        __syncthreads();
#pragma unroll
        for (int kk = 0; kk < BK; kk++) {
            float4 a0 = *(const float4*)&As[kk][ty * 8];
            float4 a1 = *(const float4*)&As[kk][ty * 8 + 4];
            float4 b0 = *(const float4*)&Bs[kk][tx * 8];
            float4 b1 = *(const float4*)&Bs[kk][tx * 8 + 4];
            float av[8] = {a0.x, a0.y, a0.z, a0.w, a1.x, a1.y, a1.z, a1.w};
            float bv[8] = {b0.x, b0.y, b0.z, b0.w, b1.x, b1.y, b1.z, b1.w};
#pragma unroll
            for (int i = 0; i < 8; i++)
#pragma unroll
                for (int j = 0; j < 8; j++) acc[i][j] = fmaf(av[i], bv[j], acc[i][j]);
        }
        __syncthreads();
    }

#pragma unroll
    for (int i = 0; i < 8; i++) {
        int m = m0 + ty * 8 + i;
        if (m >= M) continue;
#pragma unroll
        for (int j = 0; j < 8; j++) {
            int n = n0 + tx * 8 + j;
            if (n < DD) C[m * DD + n] = acc[i][j] + bias[n];
        }
    }
}

// ---------------- BatchNorm stats + normalize --------------------------------
__global__ void k_zero_stats() {
    int i = blockIdx.x * blockDim.x + threadIdx.x;
    if (i < DD) { g_sum[i] = 0.f; g_sumsq[i] = 0.f; }
}

__global__ void k_colstats(const float* __restrict__ X) {
    int c = threadIdx.x;
    if (c >= DD) return;
    int r0 = blockIdx.x * 64;
    int rend = min(r0 + 64, NN);
    float s = 0.f, ss = 0.f;
    for (int r = r0; r < rend; r++) {
        float v = X[r * DD + c];
        s += v;
        ss += v * v;
    }
    atomicAdd(&g_sum[c], s);
    atomicAdd(&g_sumsq[c], ss);
}

__global__ void k_norm(const float* __restrict__ X,
                       const float* __restrict__ gam, const float* __restrict__ bet,
                       float* __restrict__ Y)
{
    int idx = blockIdx.x * blockDim.x + threadIdx.x;
    if (idx < NN * DD) {
        int c = idx % DD;
        const float invN = 1.f / (float)NN;
        float mean = g_sum[c] * invN;
        float var = g_sumsq[c] * invN - mean * mean;
        float inv = rsqrtf(var + BN_EPS);
        float v = (X[idx] - mean) * inv * gam[c] + bet[c];
        Y[idx] = fmaxf(v, 0.f);
    }
}

// ---------------- pooling + classifier ---------------------------------------
__global__ void k_zero_pool() {
    int i = blockIdx.x * blockDim.x + threadIdx.x;
    if (i < GG * DD) g_pool[i] = 0.f;
    if (i < GG) g_cnt[i] = 0.f;
}

__global__ void k_count(const int* __restrict__ batch) {
    int n = blockIdx.x * blockDim.x + threadIdx.x;
    if (n < NN) atomicAdd(&g_cnt[batch[n]], 1.f);
}

__global__ void k_poolacc(const int* __restrict__ batch) {
    int idx = blockIdx.x * blockDim.x + threadIdx.x;
    if (idx < NN * DD) {
        int n = idx / DD;
        int d = idx - n * DD;
        atomicAdd(&g_pool[batch[n] * DD + d], g_h[idx]);
    }
}

__global__ void k_classifier(const float* __restrict__ Wc1, const float* __restrict__ bc1,
                             const float* __restrict__ Wc2, const float* __restrict__ bc2,
                             float* __restrict__ out)
{
    __shared__ float p[DD];
    __shared__ float hid[HH];
    int g = blockIdx.x;
    float cnt = fmaxf(g_cnt[g], 1.f);
    for (int c = threadIdx.x; c < DD; c += blockDim.x) p[c] = g_pool[g * DD + c] / cnt;
    __syncthreads();
    int j = threadIdx.x;
    if (j < HH) {
        float s = bc1[j];
        for (int k = 0; k < DD; k++) s = fmaf(p[k], Wc1[k * HH + j], s);
        hid[j] = fmaxf(s, 0.f);
    }
    __syncthreads();
    if (j < NCC) {
        float s = bc2[j];
        for (int k = 0; k < HH; k++) s = fmaf(hid[k], Wc2[k * NCC + j], s);
        out[g * NCC + j] = s;
    }
}

// ---------------- launch -----------------------------------------------------
extern "C" void kernel_launch(void* const* d_in, const int* in_sizes, int n_in,
                              void* d_out, int out_size)
{
    const int*   x  = (const int*)d_in[0];
    const int*   ei = (const int*)d_in[1];
    const float* edge_attr;
    const int*   batch;
    // disambiguate dict-order vs signature-order via sizes (E*EDIM vs N)
    if (in_sizes[2] == EE * EDIMM) {
        edge_attr = (const float*)d_in[2];
        batch     = (const int*)d_in[3];
    } else {
        batch     = (const int*)d_in[2];
        edge_attr = (const float*)d_in[3];
    }
    const float* node_emb = (const float*)d_in[4];
    const float* edge_W   = (const float*)d_in[5];
    const float* edge_b   = (const float*)d_in[6];
    const float* eps      = (const float*)d_in[7];
    const float* W1  = (const float*)d_in[8];
    const float* b1  = (const float*)d_in[9];
    const float* g1  = (const float*)d_in[10];
    const float* be1 = (const float*)d_in[11];
    const float* W2  = (const float*)d_in[12];
    const float* b2  = (const float*)d_in[13];
    const float* g2  = (const float*)d_in[14];
    const float* be2 = (const float*)d_in[15];
    const float* Wc1 = (const float*)d_in[16];
    const float* bc1 = (const float*)d_in[17];
    const float* Wc2 = (const float*)d_in[18];
    const float* bc2 = (const float*)d_in[19];
    float* out = (float*)d_out;

    float *p_h, *p_A, *p_B;
    cudaGetSymbolAddress((void**)&p_h, g_h);
    cudaGetSymbolAddress((void**)&p_A, g_bufA);
    cudaGetSymbolAddress((void**)&p_B, g_bufB);

    const int ND_BLOCKS = (NN * DD + 255) / 256;

    // CSR build (by dst)
    k_zero_csr<<<(NN + 256) / 256, 256>>>();
    k_hist<<<(EE + 255) / 256, 256>>>(ei);
    k_scan<<<1, 1024>>>();
    k_fill<<<(NN + 255) / 256, 256>>>();
    k_scatter<<<(EE + 255) / 256, 256>>>(ei);

    // node encoder
    k_encode<<<ND_BLOCKS, 256>>>(x, node_emb);

    dim3 ggrid((DD + BN - 1) / BN, (NN + BM - 1) / BM);
    for (int l = 0; l < LL; l++) {
        // z = (1+eps)*h + sum relu(h[src] + edgeMLP)
        k_aggregate<<<(NN + 3) / 4, 128>>>(edge_attr, edge_W, edge_b, eps, l, p_A);
        // t = z @ W1 + b1
        k_gemm_bias<<<ggrid, 256>>>(p_A, W1 + l * DD * DD, b1 + l * DD, p_B, NN);
        // BN1 + relu (in place)
        k_zero_stats<<<2, 256>>>();
        k_colstats<<<(NN + 63) / 64, 320>>>(p_B);
        k_norm<<<ND_BLOCKS, 256>>>(p_B, g1 + l * DD, be1 + l * DD, p_B);
        // t2 = y @ W2 + b2
        k_gemm_bias<<<ggrid, 256>>>(p_B, W2 + l * DD * DD, b2 + l * DD, p_A, NN);
        // BN2 + relu -> h
        k_zero_stats<<<2, 256>>>();
        k_colstats<<<(NN + 63) / 64, 320>>>(p_A);
        k_norm<<<ND_BLOCKS, 256>>>(p_A, g2 + l * DD, be2 + l * DD, p_h);
    }

    // global mean pool + classifier
    k_zero_pool<<<(GG * DD + 255) / 256, 256>>>();
    k_count<<<(NN + 255) / 256, 256>>>(batch);
    k_poolacc<<<ND_BLOCKS, 256>>>(batch);
    k_classifier<<<GG, 160>>>(Wc1, bc1, Wc2, bc2, out);
}

// round 3
// speedup vs baseline: 1.5143x; 1.5143x over previous
#include <cuda_runtime.h>
#include <cuda_bf16.h>
#include <cstdint>

#define NN   20000
#define EE   320000
#define DD   300
#define LL   5
#define VV   119
#define EDIMM 7
#define GG   128
#define NCC  6
#define HH   150
#define BN_EPS 1e-5f

// ---------------- scratch (static device memory; no runtime allocs) ----------
__device__ float g_h[NN * DD];
__device__ float g_bufA[NN * DD];
__device__ float g_bufB[NN * DD];
__device__ int   g_rowptr[NN + 1];
__device__ int   g_fill[NN];
__device__ int   g_csrc[EE];
__device__ int   g_ceid[EE];
__device__ float g_sum[DD];
__device__ float g_sumsq[DD];
__device__ float g_pool[GG * DD];
__device__ float g_cnt[GG];

// ---------------- CSR build --------------------------------------------------
__global__ void k_zero_csr() {
    int i = blockIdx.x * blockDim.x + threadIdx.x;
    if (i <= NN) g_rowptr[i] = 0;
}

__global__ void k_hist(const int* __restrict__ ei) {
    int e = blockIdx.x * blockDim.x + threadIdx.x;
    if (e < EE) {
        int dst = ei[EE + e];
        atomicAdd(&g_rowptr[dst + 1], 1);
    }
}

__global__ void k_scan() {
    // inclusive scan over g_rowptr[0..NN]; also seeds g_fill with row starts
    __shared__ int s[1024];
    const int CH = 20;
    int t = threadIdx.x;
    int base = t * CH;
    int vals[CH];
    int run = 0;
#pragma unroll
    for (int i = 0; i < CH; i++) {
        int idx = base + i;
        int v = (idx <= NN) ? g_rowptr[idx] : 0;
        run += v;
        vals[i] = run;
    }
    s[t] = run;
    __syncthreads();
    for (int off = 1; off < 1024; off <<= 1) {
        int v = (t >= off) ? s[t - off] : 0;
        __syncthreads();
        s[t] += v;
        __syncthreads();
    }
    int pre = s[t] - run;
#pragma unroll
    for (int i = 0; i < CH; i++) {
        int idx = base + i;
        if (idx <= NN) {
            int rv = pre + vals[i];
            g_rowptr[idx] = rv;
            if (idx < NN) g_fill[idx] = rv;
        }
    }
}

__global__ void k_scatter(const int* __restrict__ ei) {
    int e = blockIdx.x * blockDim.x + threadIdx.x;
    if (e < EE) {
        int src = ei[e];
        int dst = ei[EE + e];
        int pos = atomicAdd(&g_fill[dst], 1);
        g_csrc[pos] = src;
        g_ceid[pos] = e;
    }
}

// ---------------- node encoder ----------------------------------------------
__global__ void k_encode(const int* __restrict__ x, const float* __restrict__ emb) {
    int idx = blockIdx.x * blockDim.x + threadIdx.x;
    if (idx < NN * DD) {
        int n = idx / DD;
        int d = idx - n * DD;
        g_h[idx] = emb[x[n] * DD + d];
    }
}

// ---------------- GINE aggregation: warp per node, edge MLP recomputed -------
__global__ void __launch_bounds__(128) k_aggregate(
    const float* __restrict__ edge_attr,
    const float* __restrict__ edge_W,
    const float* __restrict__ edge_b,
    const float* __restrict__ eps, int layer,
    float* __restrict__ zout)
{
    int tid = threadIdx.x;
    int warp = tid >> 5, lane = tid & 31;
    int node = blockIdx.x * 4 + warp;
    if (node >= NN) return;

    float wreg[10][EDIMM];
    float ebr[10];
#pragma unroll
    for (int j = 0; j < 10; j++) {
        int d = lane + 32 * j;
        if (d < DD) {
            ebr[j] = edge_b[d];
#pragma unroll
            for (int k = 0; k < EDIMM; k++) wreg[j][k] = edge_W[k * DD + d];
        } else {
            ebr[j] = 0.f;
#pragma unroll
            for (int k = 0; k < EDIMM; k++) wreg[j][k] = 0.f;
        }
    }

    float acc[10];
#pragma unroll
    for (int j = 0; j < 10; j++) acc[j] = 0.f;

    int beg = g_rowptr[node], end = g_rowptr[node + 1];
    for (int idx = beg; idx < end; idx++) {
        int src = g_csrc[idx];
        int eid = g_ceid[idx];
        float a[EDIMM];
#pragma unroll
        for (int k = 0; k < EDIMM; k++) a[k] = edge_attr[eid * EDIMM + k];
        const float* hrow = g_h + src * DD;
#pragma unroll
        for (int j = 0; j < 10; j++) {
            int d = lane + 32 * j;
            if (d < DD) {
                float ea = ebr[j];
#pragma unroll
                for (int k = 0; k < EDIMM; k++) ea = fmaf(a[k], wreg[j][k], ea);
                float v = hrow[d] + ea;
                acc[j] += fmaxf(v, 0.f);
            }
        }
    }

    float epsv = 1.f + eps[layer];
#pragma unroll
    for (int j = 0; j < 10; j++) {
        int d = lane + 32 * j;
        if (d < DD) zout[node * DD + d] = epsv * g_h[node * DD + d] + acc[j];
    }
}

// ---------------- tf32 tensor-core GEMM + bias -------------------------------
// C[M,300] = A[M,300] @ B[300,300] + bias
// Block tile 128x160, 8 warps (4m x 2n), warp tile 32x80, BK=8, double-buffered.
#define SA 136   // As row stride (128 + 8 pad)
#define SBX 168  // Bs row stride (160 + 8 pad)
#define GBM 128
#define GBN 160

__device__ __forceinline__ float to_tf32(float x) {
    uint32_t r;
    asm("cvt.rna.tf32.f32 %0, %1;" : "=r"(r) : "f"(x));
    return __uint_as_float(r);
}

__device__ __forceinline__ void mma_tf32(float* d, const uint32_t* a, const uint32_t* b) {
    asm volatile(
        "mma.sync.aligned.m16n8k8.row.col.f32.tf32.tf32.f32 "
        "{%0,%1,%2,%3},{%4,%5,%6,%7},{%8,%9},{%0,%1,%2,%3};"
        : "+f"(d[0]), "+f"(d[1]), "+f"(d[2]), "+f"(d[3])
        : "r"(a[0]), "r"(a[1]), "r"(a[2]), "r"(a[3]), "r"(b[0]), "r"(b[1]));
}

__global__ void __launch_bounds__(256, 1) k_gemm_tc(
    const float* __restrict__ A, const float* __restrict__ B,
    const float* __restrict__ bias, float* __restrict__ C, int M)
{
    __shared__ float As[2][8 * SA];
    __shared__ float Bs[2][8 * SBX];

    int t = threadIdx.x;
    int warp = t >> 5, lane = t & 31;
    int g = lane >> 2, tq = lane & 3;
    int m0 = blockIdx.y * GBM;
    int n0 = blockIdx.x * GBN;
    int wm = (warp >> 1) * 32;
    int wn = (warp & 1) * 80;

    float c[2][10][4];
#pragma unroll
    for (int i = 0; i < 2; i++)
#pragma unroll
        for (int j = 0; j < 10; j++)
#pragma unroll
            for (int q = 0; q < 4; q++) c[i][j][q] = 0.f;

    // A staging: thread loads float4 of one row
    int lm = t >> 1;           // 0..127
    int lk4 = (t & 1) * 4;     // 0 or 4

    float av[4];
    float bv[5];

    const int ITERS = (DD + 7) / 8;  // 38

    auto loadg = [&](int k0) {
        int row = m0 + lm;
        if (row < M && (k0 + lk4) < DD) {
            float4 v = *(const float4*)(A + row * DD + k0 + lk4);
            av[0] = v.x; av[1] = v.y; av[2] = v.z; av[3] = v.w;
        } else {
            av[0] = av[1] = av[2] = av[3] = 0.f;
        }
#pragma unroll
        for (int i = 0; i < 5; i++) {
            int idx = t + 256 * i;
            int r = idx / 160, cc = idx - r * 160;
            int gr = k0 + r, gc = n0 + cc;
            bv[i] = (gr < DD && gc < DD) ? B[gr * DD + gc] : 0.f;
        }
    };
    auto store = [&](int buf) {
#pragma unroll
        for (int j = 0; j < 4; j++) As[buf][(lk4 + j) * SA + lm] = to_tf32(av[j]);
#pragma unroll
        for (int i = 0; i < 5; i++) {
            int idx = t + 256 * i;
            int r = idx / 160, cc = idx - r * 160;
            Bs[buf][r * SBX + cc] = to_tf32(bv[i]);
        }
    };

    loadg(0);
    store(0);
    __syncthreads();

    for (int it = 0; it < ITERS; it++) {
        int nxt = it + 1;
        if (nxt < ITERS) loadg(nxt * 8);

        int buf = it & 1;
        const uint32_t* Au = (const uint32_t*)As[buf];
        const uint32_t* Bu = (const uint32_t*)Bs[buf];

        uint32_t af[2][4], bf[10][2];
#pragma unroll
        for (int fm = 0; fm < 2; fm++) {
            int mb = wm + fm * 16 + g;
            af[fm][0] = Au[tq * SA + mb];
            af[fm][1] = Au[tq * SA + mb + 8];
            af[fm][2] = Au[(tq + 4) * SA + mb];
            af[fm][3] = Au[(tq + 4) * SA + mb + 8];
        }
#pragma unroll
        for (int fn = 0; fn < 10; fn++) {
            int nb = wn + fn * 8 + g;
            bf[fn][0] = Bu[tq * SBX + nb];
            bf[fn][1] = Bu[(tq + 4) * SBX + nb];
        }
#pragma unroll
        for (int fm = 0; fm < 2; fm++)
#pragma unroll
            for (int fn = 0; fn < 10; fn++)
                mma_tf32(c[fm][fn], af[fm], bf[fn]);

        if (nxt < ITERS) store(nxt & 1);
        __syncthreads();
    }

    // epilogue: bias + store (float2, cols are even so col<DD => col+1<DD)
#pragma unroll
    for (int fm = 0; fm < 2; fm++) {
        int r0 = m0 + wm + fm * 16 + g;
        int r1 = r0 + 8;
#pragma unroll
        for (int fn = 0; fn < 10; fn++) {
            int col = n0 + wn + fn * 8 + tq * 2;
            if (col < DD) {
                float bx = bias[col], by = bias[col + 1];
                if (r0 < M) {
                    float2 v = make_float2(c[fm][fn][0] + bx, c[fm][fn][1] + by);
                    *(float2*)&C[r0 * DD + col] = v;
                }
                if (r1 < M) {
                    float2 v = make_float2(c[fm][fn][2] + bx, c[fm][fn][3] + by);
                    *(float2*)&C[r1 * DD + col] = v;
                }
            }
        }
    }
}

// ---------------- BatchNorm stats + normalize --------------------------------
__global__ void k_zero_stats() {
    int i = blockIdx.x * blockDim.x + threadIdx.x;
    if (i < DD) { g_sum[i] = 0.f; g_sumsq[i] = 0.f; }
}

__global__ void k_colstats(const float* __restrict__ X) {
    int c = threadIdx.x;
    if (c >= DD) return;
    int r0 = blockIdx.x * 64;
    int rend = min(r0 + 64, NN);
    float s = 0.f, ss = 0.f;
    for (int r = r0; r < rend; r++) {
        float v = X[r * DD + c];
        s += v;
        ss += v * v;
    }
    atomicAdd(&g_sum[c], s);
    atomicAdd(&g_sumsq[c], ss);
}

__global__ void k_norm(const float* __restrict__ X,
                       const float* __restrict__ gam, const float* __restrict__ bet,
                       float* __restrict__ Y)
{
    int idx = blockIdx.x * blockDim.x + threadIdx.x;
    if (idx < NN * DD) {
        int c = idx % DD;
        const float invN = 1.f / (float)NN;
        float mean = g_sum[c] * invN;
        float var = g_sumsq[c] * invN - mean * mean;
        float inv = rsqrtf(var + BN_EPS);
        float v = (X[idx] - mean) * inv * gam[c] + bet[c];
        Y[idx] = fmaxf(v, 0.f);
    }
}

// ---------------- pooling + classifier ---------------------------------------
__global__ void k_zero_pool() {
    int i = blockIdx.x * blockDim.x + threadIdx.x;
    if (i < GG * DD) g_pool[i] = 0.f;
    if (i < GG) g_cnt[i] = 0.f;
}

__global__ void k_count(const int* __restrict__ batch) {
    int n = blockIdx.x * blockDim.x + threadIdx.x;
    if (n < NN) atomicAdd(&g_cnt[batch[n]], 1.f);
}

__global__ void k_poolacc(const int* __restrict__ batch) {
    int idx = blockIdx.x * blockDim.x + threadIdx.x;
    if (idx < NN * DD) {
        int n = idx / DD;
        int d = idx - n * DD;
        atomicAdd(&g_pool[batch[n] * DD + d], g_h[idx]);
    }
}

__global__ void k_classifier(const float* __restrict__ Wc1, const float* __restrict__ bc1,
                             const float* __restrict__ Wc2, const float* __restrict__ bc2,
                             float* __restrict__ out)
{
    __shared__ float p[DD];
    __shared__ float hid[HH];
    int g = blockIdx.x;
    float cnt = fmaxf(g_cnt[g], 1.f);
    for (int c = threadIdx.x; c < DD; c += blockDim.x) p[c] = g_pool[g * DD + c] / cnt;
    __syncthreads();
    int j = threadIdx.x;
    if (j < HH) {
        float s = bc1[j];
        for (int k = 0; k < DD; k++) s = fmaf(p[k], Wc1[k * HH + j], s);
        hid[j] = fmaxf(s, 0.f);
    }
    __syncthreads();
    if (j < NCC) {
        float s = bc2[j];
        for (int k = 0; k < HH; k++) s = fmaf(hid[k], Wc2[k * NCC + j], s);
        out[g * NCC + j] = s;
    }
}

// ---------------- launch -----------------------------------------------------
extern "C" void kernel_launch(void* const* d_in, const int* in_sizes, int n_in,
                              void* d_out, int out_size)
{
    const int*   x  = (const int*)d_in[0];
    const int*   ei = (const int*)d_in[1];
    const float* edge_attr;
    const int*   batch;
    if (in_sizes[2] == EE * EDIMM) {
        edge_attr = (const float*)d_in[2];
        batch     = (const int*)d_in[3];
    } else {
        batch     = (const int*)d_in[2];
        edge_attr = (const float*)d_in[3];
    }
    const float* node_emb = (const float*)d_in[4];
    const float* edge_W   = (const float*)d_in[5];
    const float* edge_b   = (const float*)d_in[6];
    const float* eps      = (const float*)d_in[7];
    const float* W1  = (const float*)d_in[8];
    const float* b1  = (const float*)d_in[9];
    const float* g1  = (const float*)d_in[10];
    const float* be1 = (const float*)d_in[11];
    const float* W2  = (const float*)d_in[12];
    const float* b2  = (const float*)d_in[13];
    const float* g2  = (const float*)d_in[14];
    const float* be2 = (const float*)d_in[15];
    const float* Wc1 = (const float*)d_in[16];
    const float* bc1 = (const float*)d_in[17];
    const float* Wc2 = (const float*)d_in[18];
    const float* bc2 = (const float*)d_in[19];
    float* out = (float*)d_out;

    float *p_h, *p_A, *p_B;
    cudaGetSymbolAddress((void**)&p_h, g_h);
    cudaGetSymbolAddress((void**)&p_A, g_bufA);
    cudaGetSymbolAddress((void**)&p_B, g_bufB);

    const int ND_BLOCKS = (NN * DD + 255) / 256;

    // CSR build (by dst)
    k_zero_csr<<<(NN + 256) / 256, 256>>>();
    k_hist<<<(EE + 255) / 256, 256>>>(ei);
    k_scan<<<1, 1024>>>();
    k_scatter<<<(EE + 255) / 256, 256>>>(ei);

    // node encoder
    k_encode<<<ND_BLOCKS, 256>>>(x, node_emb);

    dim3 ggrid((DD + GBN - 1) / GBN, (NN + GBM - 1) / GBM);  // (2, 157)
    for (int l = 0; l < LL; l++) {
        k_aggregate<<<(NN + 3) / 4, 128>>>(edge_attr, edge_W, edge_b, eps, l, p_A);
        k_gemm_tc<<<ggrid, 256>>>(p_A, W1 + l * DD * DD, b1 + l * DD, p_B, NN);
        k_zero_stats<<<2, 256>>>();
        k_colstats<<<(NN + 63) / 64, 320>>>(p_B);
        k_norm<<<ND_BLOCKS, 256>>>(p_B, g1 + l * DD, be1 + l * DD, p_B);
        k_gemm_tc<<<ggrid, 256>>>(p_B, W2 + l * DD * DD, b2 + l * DD, p_A, NN);
        k_zero_stats<<<2, 256>>>();
        k_colstats<<<(NN + 63) / 64, 320>>>(p_A);
        k_norm<<<ND_BLOCKS, 256>>>(p_A, g2 + l * DD, be2 + l * DD, p_h);
    }

    k_zero_pool<<<(GG * DD + 255) / 256, 256>>>();
    k_count<<<(NN + 255) / 256, 256>>>(batch);
    k_poolacc<<<ND_BLOCKS, 256>>>(batch);
    k_classifier<<<GG, 160>>>(Wc1, bc1, Wc2, bc2, out);
}

// round 4
// speedup vs baseline: 1.6685x; 1.1018x over previous
#include <cuda_runtime.h>
#include <cuda_bf16.h>
#include <cstdint>

#define NN   20000
#define EE   320000
#define DD   300
#define LL   5
#define VV   119
#define EDIMM 7
#define GG   128
#define NCC  6
#define HH   150
#define BN_EPS 1e-5f

// ---------------- scratch ----------------------------------------------------
__device__ float g_h[NN * DD];
__device__ float g_bufA[NN * DD];
__device__ float g_bufB[NN * DD];
__device__ int   g_rowptr[NN + 1];
__device__ int   g_fill[NN];
__device__ int   g_csrc[EE];
__device__ int   g_ceid[EE];
__device__ float g_sum[DD];
__device__ float g_sumsq[DD];
__device__ float g_alpha[DD];
__device__ float g_beta[DD];
__device__ float g_pool[GG * DD];
__device__ int   g_gstart[GG + 1];

// ---------------- CSR build --------------------------------------------------
__global__ void k_zero_csr() {
    int i = blockIdx.x * blockDim.x + threadIdx.x;
    if (i <= NN) g_rowptr[i] = 0;
}

__global__ void k_hist(const int* __restrict__ ei) {
    int e = blockIdx.x * blockDim.x + threadIdx.x;
    if (e < EE) atomicAdd(&g_rowptr[ei[EE + e] + 1], 1);
}

__global__ void k_scan() {
    __shared__ int s[1024];
    const int CH = 20;
    int t = threadIdx.x;
    int base = t * CH;
    int vals[CH];
    int run = 0;
#pragma unroll
    for (int i = 0; i < CH; i++) {
        int idx = base + i;
        int v = (idx <= NN) ? g_rowptr[idx] : 0;
        run += v;
        vals[i] = run;
    }
    s[t] = run;
    __syncthreads();
    for (int off = 1; off < 1024; off <<= 1) {
        int v = (t >= off) ? s[t - off] : 0;
        __syncthreads();
        s[t] += v;
        __syncthreads();
    }
    int pre = s[t] - run;
#pragma unroll
    for (int i = 0; i < CH; i++) {
        int idx = base + i;
        if (idx <= NN) {
            int rv = pre + vals[i];
            g_rowptr[idx] = rv;
            if (idx < NN) g_fill[idx] = rv;
        }
    }
}

__global__ void k_scatter(const int* __restrict__ ei) {
    int e = blockIdx.x * blockDim.x + threadIdx.x;
    if (e < EE) {
        int src = ei[e];
        int dst = ei[EE + e];
        int pos = atomicAdd(&g_fill[dst], 1);
        g_csrc[pos] = src;
        g_ceid[pos] = e;
    }
}

// ---------------- node encoder ----------------------------------------------
__global__ void k_encode(const int* __restrict__ x, const float* __restrict__ emb) {
    int idx = blockIdx.x * blockDim.x + threadIdx.x;
    if (idx < NN * DD) {
        int n = idx / DD;
        int d = idx - n * DD;
        g_h[idx] = emb[x[n] * DD + d];
    }
}

// ---------------- GINE aggregation -------------------------------------------
__global__ void __launch_bounds__(128) k_aggregate(
    const float* __restrict__ edge_attr,
    const float* __restrict__ edge_W,
    const float* __restrict__ edge_b,
    const float* __restrict__ eps, int layer,
    float* __restrict__ zout)
{
    int tid = threadIdx.x;
    int warp = tid >> 5, lane = tid & 31;
    int node = blockIdx.x * 4 + warp;
    if (node >= NN) return;

    float wreg[10][EDIMM];
    float ebr[10];
#pragma unroll
    for (int j = 0; j < 10; j++) {
        int d = lane + 32 * j;
        if (d < DD) {
            ebr[j] = edge_b[d];
#pragma unroll
            for (int k = 0; k < EDIMM; k++) wreg[j][k] = edge_W[k * DD + d];
        } else {
            ebr[j] = 0.f;
#pragma unroll
            for (int k = 0; k < EDIMM; k++) wreg[j][k] = 0.f;
        }
    }

    float acc[10];
#pragma unroll
    for (int j = 0; j < 10; j++) acc[j] = 0.f;

    int beg = g_rowptr[node], end = g_rowptr[node + 1];
    for (int idx = beg; idx < end; idx++) {
        int src = g_csrc[idx];
        int eid = g_ceid[idx];
        float a[EDIMM];
#pragma unroll
        for (int k = 0; k < EDIMM; k++) a[k] = edge_attr[eid * EDIMM + k];
        const float* hrow = g_h + src * DD;
#pragma unroll
        for (int j = 0; j < 10; j++) {
            int d = lane + 32 * j;
            if (d < DD) {
                float ea = ebr[j];
#pragma unroll
                for (int k = 0; k < EDIMM; k++) ea = fmaf(a[k], wreg[j][k], ea);
                acc[j] += fmaxf(hrow[d] + ea, 0.f);
            }
        }
    }

    float epsv = 1.f + eps[layer];
#pragma unroll
    for (int j = 0; j < 10; j++) {
        int d = lane + 32 * j;
        if (d < DD) zout[node * DD + d] = epsv * g_h[node * DD + d] + acc[j];
    }
}

// ---------------- tf32 tensor-core GEMM, cp.async pipeline, fused BN ---------
#define GBM 128
#define GBN 160
#define NS  3
#define AST 12     // As floats per m-row (8 used + 4 pad) -> conflict-free
#define BST 168    // Bs floats per k-row (160 + 8 pad)   -> conflict-free

__device__ __forceinline__ void cp_async16(uint32_t dst, const void* src, bool pred) {
    int sz = pred ? 16 : 0;
    asm volatile("cp.async.cg.shared.global [%0], [%1], 16, %2;"
                 :: "r"(dst), "l"(src), "r"(sz));
}
__device__ __forceinline__ void cp_commit() { asm volatile("cp.async.commit_group;"); }
template <int N> __device__ __forceinline__ void cp_wait() {
    asm volatile("cp.async.wait_group %0;" :: "n"(N));
}

__device__ __forceinline__ uint32_t to_tf32u(float x) {
    uint32_t r;
    asm("cvt.rna.tf32.f32 %0, %1;" : "=r"(r) : "f"(x));
    return r;
}

__device__ __forceinline__ void mma_tf32(float* d, const uint32_t* a, const uint32_t* b) {
    asm volatile(
        "mma.sync.aligned.m16n8k8.row.col.f32.tf32.tf32.f32 "
        "{%0,%1,%2,%3},{%4,%5,%6,%7},{%8,%9},{%0,%1,%2,%3};"
        : "+f"(d[0]), "+f"(d[1]), "+f"(d[2]), "+f"(d[3])
        : "r"(a[0]), "r"(a[1]), "r"(a[2]), "r"(a[3]), "r"(b[0]), "r"(b[1]));
}

template <bool FUSE_NORM>
__global__ void __launch_bounds__(256, 1) k_gemm(
    const float* __restrict__ A, const float* __restrict__ B,
    const float* __restrict__ bias, float* __restrict__ C, int M)
{
    __shared__ float As[NS][GBM * AST];
    __shared__ float Bs[NS][8 * BST];
    __shared__ float s_sum[GBN], s_ssq[GBN];

    int t = threadIdx.x;
    int warp = t >> 5, lane = t & 31;
    int g = lane >> 2, tq = lane & 3;
    int m0 = blockIdx.y * GBM;
    int n0 = blockIdx.x * GBN;
    int wm = (warp >> 1) * 32;
    int wn = (warp & 1) * 80;

    if (t < GBN) { s_sum[t] = 0.f; s_ssq[t] = 0.f; }

    uint32_t asb = (uint32_t)__cvta_generic_to_shared(&As[0][0]);
    uint32_t bsb = (uint32_t)__cvta_generic_to_shared(&Bs[0][0]);

    // per-thread load coordinates
    int lm = t >> 1, lkq = (t & 1) * 4;  // A: one 16B chunk
    const int ITERS = (DD + 7) / 8;      // 38

    auto issue = [&](int s, int k0) {
        bool pa = (m0 + lm < M) && (k0 + lkq < DD);
        cp_async16(asb + (s * GBM * AST + lm * AST + lkq) * 4,
                   A + (size_t)(m0 + lm) * DD + k0 + lkq, pa);
#pragma unroll
        for (int i = 0; i < 2; i++) {
            int q = t + 256 * i;
            if (q < 320) {
                int r = q / 40, c4 = (q - r * 40) * 4;
                bool pb = (k0 + r < DD) && (n0 + c4 < DD);
                cp_async16(bsb + (s * 8 * BST + r * BST + c4) * 4,
                           B + (size_t)(k0 + r) * DD + n0 + c4, pb);
            }
        }
        cp_commit();
    };

    float c[2][10][4];
#pragma unroll
    for (int i = 0; i < 2; i++)
#pragma unroll
        for (int j = 0; j < 10; j++)
#pragma unroll
            for (int q = 0; q < 4; q++) c[i][j][q] = 0.f;

    issue(0, 0);
    issue(1, 8);

    for (int it = 0; it < ITERS; it++) {
        cp_wait<NS - 2>();
        __syncthreads();

        int pre = it + NS - 1;
        if (pre < ITERS) issue(pre % NS, pre * 8);
        else cp_commit();

        int s = it % NS;
        int k0 = it * 8;
        const float* Af = As[s];
        const float* Bf = Bs[s];

        // A fragments (+ optional fused BN-norm+ReLU on A)
        uint32_t af[2][4];
        float al0 = 0.f, be0 = 0.f, al1 = 0.f, be1 = 0.f;
        if (FUSE_NORM) {
            int ka0 = k0 + tq, ka1 = k0 + tq + 4;
            if (ka0 < DD) { al0 = g_alpha[ka0]; be0 = g_beta[ka0]; }
            if (ka1 < DD) { al1 = g_alpha[ka1]; be1 = g_beta[ka1]; }
        }
#pragma unroll
        for (int fm = 0; fm < 2; fm++) {
            int mb = wm + fm * 16 + g;
            float a0 = Af[mb * AST + tq];
            float a1 = Af[(mb + 8) * AST + tq];
            float a2 = Af[mb * AST + tq + 4];
            float a3 = Af[(mb + 8) * AST + tq + 4];
            if (FUSE_NORM) {
                a0 = fmaxf(fmaf(a0, al0, be0), 0.f);
                a1 = fmaxf(fmaf(a1, al0, be0), 0.f);
                a2 = fmaxf(fmaf(a2, al1, be1), 0.f);
                a3 = fmaxf(fmaf(a3, al1, be1), 0.f);
            }
            af[fm][0] = to_tf32u(a0);
            af[fm][1] = to_tf32u(a1);
            af[fm][2] = to_tf32u(a2);
            af[fm][3] = to_tf32u(a3);
        }
        // B fragments
        uint32_t bf[10][2];
#pragma unroll
        for (int fn = 0; fn < 10; fn++) {
            int nb = wn + fn * 8 + g;
            bf[fn][0] = to_tf32u(Bf[tq * BST + nb]);
            bf[fn][1] = to_tf32u(Bf[(tq + 4) * BST + nb]);
        }
#pragma unroll
        for (int fm = 0; fm < 2; fm++)
#pragma unroll
            for (int fn = 0; fn < 10; fn++)
                mma_tf32(c[fm][fn], af[fm], bf[fn]);
    }

    // ---- epilogue: bias + C store + BN stats (shuffle -> smem -> global) ----
#pragma unroll
    for (int fm = 0; fm < 2; fm++) {
        int r0 = m0 + wm + fm * 16 + g;
        int r1 = r0 + 8;
        bool v0 = r0 < M, v1 = r1 < M;
#pragma unroll
        for (int fn = 0; fn < 10; fn++) {
            int col = n0 + wn + fn * 8 + tq * 2;
            bool cv = col < DD;
            float bx = 0.f, by = 0.f;
            if (cv) { bx = bias[col]; by = bias[col + 1]; }
            float c00 = c[fm][fn][0] + bx, c01 = c[fm][fn][1] + by;
            float c10 = c[fm][fn][2] + bx, c11 = c[fm][fn][3] + by;
            if (cv && v0) *(float2*)&C[(size_t)r0 * DD + col] = make_float2(c00, c01);
            if (cv && v1) *(float2*)&C[(size_t)r1 * DD + col] = make_float2(c10, c11);

            float s0 = (v0 ? c00 : 0.f) + (v1 ? c10 : 0.f);
            float q0 = (v0 ? c00 * c00 : 0.f) + (v1 ? c10 * c10 : 0.f);
            float s1 = (v0 ? c01 : 0.f) + (v1 ? c11 : 0.f);
            float q1 = (v0 ? c01 * c01 : 0.f) + (v1 ? c11 * c11 : 0.f);
#pragma unroll
            for (int msk = 4; msk <= 16; msk <<= 1) {
                s0 += __shfl_xor_sync(0xffffffffu, s0, msk);
                q0 += __shfl_xor_sync(0xffffffffu, q0, msk);
                s1 += __shfl_xor_sync(0xffffffffu, s1, msk);
                q1 += __shfl_xor_sync(0xffffffffu, q1, msk);
            }
            if (g == 0 && cv) {
                int si = wn + fn * 8 + tq * 2;
                atomicAdd(&s_sum[si], s0);
                atomicAdd(&s_ssq[si], q0);
                atomicAdd(&s_sum[si + 1], s1);
                atomicAdd(&s_ssq[si + 1], q1);
            }
        }
    }
    __syncthreads();
    if (t < GBN) {
        int col = n0 + t;
        if (col < DD) {
            atomicAdd(&g_sum[col], s_sum[t]);
            atomicAdd(&g_sumsq[col], s_ssq[t]);
        }
    }
}

// ---------------- BN helpers -------------------------------------------------
__global__ void k_zero_stats() {
    int i = blockIdx.x * blockDim.x + threadIdx.x;
    if (i < DD) { g_sum[i] = 0.f; g_sumsq[i] = 0.f; }
}

__global__ void k_finstats(const float* __restrict__ gam, const float* __restrict__ bet) {
    int c = threadIdx.x;
    if (c < DD) {
        const float invN = 1.f / (float)NN;
        float mean = g_sum[c] * invN;
        float var = g_sumsq[c] * invN - mean * mean;
        float a = rsqrtf(var + BN_EPS) * gam[c];
        g_alpha[c] = a;
        g_beta[c] = bet[c] - mean * a;
    }
}

// h = relu(X * alpha + beta), vectorized
__global__ void k_norm2(const float* __restrict__ X, float* __restrict__ Y) {
    int idx = blockIdx.x * blockDim.x + threadIdx.x;
    if (idx < NN * (DD / 4)) {
        float4 x = ((const float4*)X)[idx];
        int c4 = (idx % (DD / 4)) * 4;
        float4 y;
        y.x = fmaxf(fmaf(x.x, g_alpha[c4],     g_beta[c4]),     0.f);
        y.y = fmaxf(fmaf(x.y, g_alpha[c4 + 1], g_beta[c4 + 1]), 0.f);
        y.z = fmaxf(fmaf(x.z, g_alpha[c4 + 2], g_beta[c4 + 2]), 0.f);
        y.w = fmaxf(fmaf(x.w, g_alpha[c4 + 3], g_beta[c4 + 3]), 0.f);
        ((float4*)Y)[idx] = y;
    }
}

// ---------------- pooling (batch sorted -> contiguous segments) --------------
__global__ void k_bounds(const int* __restrict__ batch) {
    int g = blockIdx.x * blockDim.x + threadIdx.x;
    if (g <= GG) {
        int lo = 0, hi = NN;
        while (lo < hi) {
            int mid = (lo + hi) >> 1;
            if (batch[mid] < g) lo = mid + 1; else hi = mid;
        }
        g_gstart[g] = lo;
    }
}

__global__ void __launch_bounds__(320) k_pool2() {
    int g = blockIdx.x;
    int t = threadIdx.x;
    int s = g_gstart[g], e = g_gstart[g + 1];
    if (t < DD) {
        float acc = 0.f;
        for (int r = s; r < e; r++) acc += g_h[(size_t)r * DD + t];
        float cnt = fmaxf((float)(e - s), 1.f);
        g_pool[g * DD + t] = acc / cnt;
    }
}

__global__ void k_classifier(const float* __restrict__ Wc1, const float* __restrict__ bc1,
                             const float* __restrict__ Wc2, const float* __restrict__ bc2,
                             float* __restrict__ out)
{
    __shared__ float p[DD];
    __shared__ float hid[HH];
    int g = blockIdx.x;
    for (int c = threadIdx.x; c < DD; c += blockDim.x) p[c] = g_pool[g * DD + c];
    __syncthreads();
    int j = threadIdx.x;
    if (j < HH) {
        float s = bc1[j];
        for (int k = 0; k < DD; k++) s = fmaf(p[k], Wc1[k * HH + j], s);
        hid[j] = fmaxf(s, 0.f);
    }
    __syncthreads();
    if (j < NCC) {
        float s = bc2[j];
        for (int k = 0; k < HH; k++) s = fmaf(hid[k], Wc2[k * NCC + j], s);
        out[g * NCC + j] = s;
    }
}

// ---------------- launch -----------------------------------------------------
extern "C" void kernel_launch(void* const* d_in, const int* in_sizes, int n_in,
                              void* d_out, int out_size)
{
    const int*   x  = (const int*)d_in[0];
    const int*   ei = (const int*)d_in[1];
    const float* edge_attr;
    const int*   batch;
    if (in_sizes[2] == EE * EDIMM) {
        edge_attr = (const float*)d_in[2];
        batch     = (const int*)d_in[3];
    } else {
        batch     = (const int*)d_in[2];
        edge_attr = (const float*)d_in[3];
    }
    const float* node_emb = (const float*)d_in[4];
    const float* edge_W   = (const float*)d_in[5];
    const float* edge_b   = (const float*)d_in[6];
    const float* eps      = (const float*)d_in[7];
    const float* W1  = (const float*)d_in[8];
    const float* b1  = (const float*)d_in[9];
    const float* g1  = (const float*)d_in[10];
    const float* be1 = (const float*)d_in[11];
    const float* W2  = (const float*)d_in[12];
    const float* b2  = (const float*)d_in[13];
    const float* g2  = (const float*)d_in[14];
    const float* be2 = (const float*)d_in[15];
    const float* Wc1 = (const float*)d_in[16];
    const float* bc1 = (const float*)d_in[17];
    const float* Wc2 = (const float*)d_in[18];
    const float* bc2 = (const float*)d_in[19];
    float* out = (float*)d_out;

    float *p_h, *p_A, *p_B;
    cudaGetSymbolAddress((void**)&p_h, g_h);
    cudaGetSymbolAddress((void**)&p_A, g_bufA);
    cudaGetSymbolAddress((void**)&p_B, g_bufB);

    const int ND_BLOCKS = (NN * DD + 255) / 256;

    // CSR build (by dst)
    k_zero_csr<<<(NN + 256) / 256, 256>>>();
    k_hist<<<(EE + 255) / 256, 256>>>(ei);
    k_scan<<<1, 1024>>>();
    k_scatter<<<(EE + 255) / 256, 256>>>(ei);

    // node encoder
    k_encode<<<ND_BLOCKS, 256>>>(x, node_emb);

    dim3 ggrid((DD + GBN - 1) / GBN, (NN + GBM - 1) / GBM);  // (2, 157)
    for (int l = 0; l < LL; l++) {
        k_aggregate<<<(NN + 3) / 4, 128>>>(edge_attr, edge_W, edge_b, eps, l, p_A);
        k_zero_stats<<<2, 256>>>();
        k_gemm<false><<<ggrid, 256>>>(p_A, W1 + l * DD * DD, b1 + l * DD, p_B, NN);
        k_finstats<<<1, 320>>>(g1 + l * DD, be1 + l * DD);
        k_zero_stats<<<2, 256>>>();
        k_gemm<true><<<ggrid, 256>>>(p_B, W2 + l * DD * DD, b2 + l * DD, p_A, NN);
        k_finstats<<<1, 320>>>(g2 + l * DD, be2 + l * DD);
        k_norm2<<<(NN * (DD / 4) + 255) / 256, 256>>>(p_A, p_h);
    }

    // pooling + classifier
    k_bounds<<<1, 160>>>(batch);
    k_pool2<<<GG, 320>>>();
    k_classifier<<<GG, 160>>>(Wc1, bc1, Wc2, bc2, out);
}

// round 6
// speedup vs baseline: 1.9261x; 1.1544x over previous
#include <cuda_runtime.h>
#include <cuda_bf16.h>
#include <cstdint>

#define NN   20000
#define EE   320000
#define DD   300
#define LL   5
#define VV   119
#define EDIMM 7
#define GG   128
#define NCC  6
#define HH   150
#define BN_EPS 1e-5f

#define KPAD 304            // padded+permuted activation K stride
#define KP   320            // padded weight dims
#define NGRP 38             // K groups of 8 (304/8)

// ---------------- scratch ----------------------------------------------------
__device__ float g_h[NN * DD];
__device__ float g_P[NN * KPAD];       // permuted tf32 activations (GEMM A)
__device__ float g_C[NN * DD];         // GEMM output
__device__ float g_Wt[10 * KP * KP];   // transposed, permuted, tf32 weights [n][k]
__device__ int   g_rowptr[NN + 1];
__device__ int   g_fill[NN];
__device__ int   g_csrc[EE];
__device__ int   g_ceid[EE];
__device__ float g_sum[DD];
__device__ float g_sumsq[DD];
__device__ float g_alpha[DD];
__device__ float g_beta[DD];
__device__ float g_pool[GG * DD];
__device__ int   g_gstart[GG + 1];

// ---------------- helpers ----------------------------------------------------
__device__ __forceinline__ void cp_async16(uint32_t dst, const void* src, bool pred) {
    int sz = pred ? 16 : 0;
    asm volatile("cp.async.cg.shared.global [%0], [%1], 16, %2;"
                 :: "r"(dst), "l"(src), "r"(sz));
}
__device__ __forceinline__ void cp_commit() { asm volatile("cp.async.commit_group;"); }
template <int N> __device__ __forceinline__ void cp_wait() {
    asm volatile("cp.async.wait_group %0;" :: "n"(N));
}
__device__ __forceinline__ float to_tf32f(float x) {
    uint32_t r;
    asm("cvt.rna.tf32.f32 %0, %1;" : "=r"(r) : "f"(x));
    return __uint_as_float(r);
}
__device__ __forceinline__ void mma_tf32(float* d, const uint32_t* a, const uint32_t* b) {
    asm volatile(
        "mma.sync.aligned.m16n8k8.row.col.f32.tf32.tf32.f32 "
        "{%0,%1,%2,%3},{%4,%5,%6,%7},{%8,%9},{%0,%1,%2,%3};"
        : "+f"(d[0]), "+f"(d[1]), "+f"(d[2]), "+f"(d[3])
        : "r"(a[0]), "r"(a[1]), "r"(a[2]), "r"(a[3]), "r"(b[0]), "r"(b[1]));
}

// ---------------- CSR build --------------------------------------------------
__global__ void k_zero_csr() {
    int i = blockIdx.x * blockDim.x + threadIdx.x;
    if (i <= NN) g_rowptr[i] = 0;
}
__global__ void k_hist(const int* __restrict__ ei) {
    int e = blockIdx.x * blockDim.x + threadIdx.x;
    if (e < EE) atomicAdd(&g_rowptr[ei[EE + e] + 1], 1);
}
__global__ void k_scan() {
    __shared__ int s[1024];
    const int CH = 20;
    int t = threadIdx.x;
    int base = t * CH;
    int vals[CH];
    int run = 0;
#pragma unroll
    for (int i = 0; i < CH; i++) {
        int idx = base + i;
        int v = (idx <= NN) ? g_rowptr[idx] : 0;
        run += v;
        vals[i] = run;
    }
    s[t] = run;
    __syncthreads();
    for (int off = 1; off < 1024; off <<= 1) {
        int v = (t >= off) ? s[t - off] : 0;
        __syncthreads();
        s[t] += v;
        __syncthreads();
    }
    int pre = s[t] - run;
#pragma unroll
    for (int i = 0; i < CH; i++) {
        int idx = base + i;
        if (idx <= NN) {
            int rv = pre + vals[i];
            g_rowptr[idx] = rv;
            if (idx < NN) g_fill[idx] = rv;
        }
    }
}
__global__ void k_scatter(const int* __restrict__ ei) {
    int e = blockIdx.x * blockDim.x + threadIdx.x;
    if (e < EE) {
        int src = ei[e];
        int dst = ei[EE + e];
        int pos = atomicAdd(&g_fill[dst], 1);
        g_csrc[pos] = src;
        g_ceid[pos] = e;
    }
}

// ---------------- node encoder ----------------------------------------------
__global__ void k_encode(const int* __restrict__ x, const float* __restrict__ emb) {
    int idx = blockIdx.x * blockDim.x + threadIdx.x;
    if (idx < NN * DD) {
        int n = idx / DD;
        int d = idx - n * DD;
        g_h[idx] = emb[x[n] * DD + d];
    }
}

// ---------------- weight prep: transpose + pad + tf32 + k-perm ---------------
// g_Wt[s][n][ks] = tf32(W[kl][n]) where kl = inverse-perm(ks); zero padded.
__global__ void k_twist(const float* __restrict__ W1, const float* __restrict__ W2) {
    int s = blockIdx.y;
    const float* W = (s < LL) ? (W1 + s * DD * DD) : (W2 + (s - LL) * DD * DD);
    int idx = blockIdx.x * blockDim.x + threadIdx.x;
    if (idx < KP * KP) {
        int n = idx / KP, ks = idx - n * KP;
        int j = ks & 7;
        int kl = (ks & ~7) | ((j & 1) ? 4 + (j >> 1) : (j >> 1));
        float v = (n < DD && kl < DD) ? to_tf32f(W[kl * DD + n]) : 0.f;
        g_Wt[(size_t)s * KP * KP + idx] = v;
    }
}

// ---------------- GINE aggregation (tf32-rounded, permuted store) ------------
__global__ void __launch_bounds__(128) k_aggregate(
    const float* __restrict__ edge_attr,
    const float* __restrict__ edge_W,
    const float* __restrict__ edge_b,
    const float* __restrict__ eps, int layer,
    float* __restrict__ zout)   // stride KPAD, permuted
{
    int tid = threadIdx.x;
    int warp = tid >> 5, lane = tid & 31;
    int node = blockIdx.x * 4 + warp;
    if (node >= NN) return;

    float wreg[10][EDIMM];
    float ebr[10];
#pragma unroll
    for (int j = 0; j < 10; j++) {
        int d = lane + 32 * j;
        if (d < DD) {
            ebr[j] = edge_b[d];
#pragma unroll
            for (int k = 0; k < EDIMM; k++) wreg[j][k] = edge_W[k * DD + d];
        } else {
            ebr[j] = 0.f;
#pragma unroll
            for (int k = 0; k < EDIMM; k++) wreg[j][k] = 0.f;
        }
    }

    float acc[10];
#pragma unroll
    for (int j = 0; j < 10; j++) acc[j] = 0.f;

    int beg = g_rowptr[node], end = g_rowptr[node + 1];
    for (int idx = beg; idx < end; idx++) {
        int src = g_csrc[idx];
        int eid = g_ceid[idx];
        float a[EDIMM];
#pragma unroll
        for (int k = 0; k < EDIMM; k++) a[k] = edge_attr[eid * EDIMM + k];
        const float* hrow = g_h + src * DD;
#pragma unroll
        for (int j = 0; j < 10; j++) {
            int d = lane + 32 * j;
            if (d < DD) {
                float ea = ebr[j];
#pragma unroll
                for (int k = 0; k < EDIMM; k++) ea = fmaf(a[k], wreg[j][k], ea);
                acc[j] += fmaxf(hrow[d] + ea, 0.f);
            }
        }
    }

    float epsv = 1.f + eps[layer];
    int lane_off = 2 * (lane & 3) + ((lane >> 2) & 1);
    int lane_hi = lane & 24;
#pragma unroll
    for (int j = 0; j < 10; j++) {
        int d = lane + 32 * j;
        if (d < DD) {
            float v = to_tf32f(epsv * g_h[node * DD + d] + acc[j]);
            zout[(size_t)node * KPAD + 32 * j + lane_hi + lane_off] = v;
        }
    }
    // zero pad store positions of logical k 300..303 (perm'd: 297,299,301,303)
    if (lane < 4) zout[(size_t)node * KPAD + 297 + 2 * lane] = 0.f;
}

// ---------------- tf32 mma.sync GEMM, permuted operands, fused BN stats ------
// C[M,300] = P[M,304] @ Wt^T + bias ; P perm'd tf32, Wt [n:320][k:320] perm'd tf32.
#define NS 3

__global__ void __launch_bounds__(256) k_gemm_tc(
    const float* __restrict__ A,   // stride KPAD
    const float* __restrict__ Bt,  // stride KP, [n][k]
    const float* __restrict__ bias, float* __restrict__ C, int M)
{
    __shared__ float As[NS][128 * 8];
    __shared__ float Bs[NS][160 * 8];
    __shared__ float s_sum[160], s_ssq[160];

    int t = threadIdx.x;
    int warp = t >> 5, lane = t & 31;
    int g = lane >> 2, tq = lane & 3;
    int m0 = blockIdx.y * 128;
    int n0 = blockIdx.x * 160;
    int wm = (warp >> 1) * 32;
    int wn = (warp & 1) * 80;

    if (t < 160) { s_sum[t] = 0.f; s_ssq[t] = 0.f; }

    uint32_t asb = (uint32_t)__cvta_generic_to_shared(&As[0][0]);
    uint32_t bsb = (uint32_t)__cvta_generic_to_shared(&Bs[0][0]);

    auto issue = [&](int s, int it) {
        // A: 128 rows x 32B = 256 chunks (1/thread)
        {
            int row = t >> 1, half = t & 1;
            bool p = (m0 + row) < M;
            cp_async16(asb + (s * 1024 + row * 8 + half * 4) * 4,
                       A + (size_t)(m0 + row) * KPAD + it * 8 + half * 4, p);
        }
        // B: 160 rows x 32B = 320 chunks
#pragma unroll
        for (int i = 0; i < 2; i++) {
            int q = t + 256 * i;
            if (q < 320) {
                int row = q >> 1, half = q & 1;
                cp_async16(bsb + (s * 1280 + row * 8 + half * 4) * 4,
                           Bt + (size_t)(n0 + row) * KP + it * 8 + half * 4, true);
            }
        }
        cp_commit();
    };

    float c[2][10][4];
#pragma unroll
    for (int i = 0; i < 2; i++)
#pragma unroll
        for (int j = 0; j < 10; j++)
#pragma unroll
            for (int q = 0; q < 4; q++) c[i][j][q] = 0.f;

    issue(0, 0);
    issue(1, 1);

    for (int it = 0; it < NGRP; it++) {
        cp_wait<NS - 2>();
        __syncthreads();

        int pre = it + NS - 1;
        if (pre < NGRP) issue(pre % NS, pre);
        else cp_commit();

        const float* Af = As[it % NS];
        const float* Bf = Bs[it % NS];

        uint32_t af[2][4];
#pragma unroll
        for (int fm = 0; fm < 2; fm++) {
            int mb = wm + fm * 16 + g;
            float2 lo = *(const float2*)&Af[mb * 8 + 2 * tq];
            float2 hi = *(const float2*)&Af[(mb + 8) * 8 + 2 * tq];
            af[fm][0] = __float_as_uint(lo.x);
            af[fm][1] = __float_as_uint(hi.x);
            af[fm][2] = __float_as_uint(lo.y);
            af[fm][3] = __float_as_uint(hi.y);
        }
        uint32_t bf[10][2];
#pragma unroll
        for (int fn = 0; fn < 10; fn++) {
            int nb = wn + fn * 8 + g;
            float2 b2 = *(const float2*)&Bf[nb * 8 + 2 * tq];
            bf[fn][0] = __float_as_uint(b2.x);
            bf[fn][1] = __float_as_uint(b2.y);
        }
#pragma unroll
        for (int fm = 0; fm < 2; fm++)
#pragma unroll
            for (int fn = 0; fn < 10; fn++)
                mma_tf32(c[fm][fn], af[fm], bf[fn]);
    }

    // ---- epilogue: bias + store + BN stats ----
#pragma unroll
    for (int fm = 0; fm < 2; fm++) {
        int r0 = m0 + wm + fm * 16 + g;
        int r1 = r0 + 8;
        bool v0 = r0 < M, v1 = r1 < M;
#pragma unroll
        for (int fn = 0; fn < 10; fn++) {
            int col = n0 + wn + fn * 8 + tq * 2;
            bool cv = col < DD;
            float bx = 0.f, by = 0.f;
            if (cv) { bx = bias[col]; by = bias[col + 1]; }
            float c00 = c[fm][fn][0] + bx, c01 = c[fm][fn][1] + by;
            float c10 = c[fm][fn][2] + bx, c11 = c[fm][fn][3] + by;
            if (cv && v0) *(float2*)&C[(size_t)r0 * DD + col] = make_float2(c00, c01);
            if (cv && v1) *(float2*)&C[(size_t)r1 * DD + col] = make_float2(c10, c11);

            float s0 = (v0 ? c00 : 0.f) + (v1 ? c10 : 0.f);
            float q0 = (v0 ? c00 * c00 : 0.f) + (v1 ? c10 * c10 : 0.f);
            float s1 = (v0 ? c01 : 0.f) + (v1 ? c11 : 0.f);
            float q1 = (v0 ? c01 * c01 : 0.f) + (v1 ? c11 * c11 : 0.f);
#pragma unroll
            for (int msk = 4; msk <= 16; msk <<= 1) {
                s0 += __shfl_xor_sync(0xffffffffu, s0, msk);
                q0 += __shfl_xor_sync(0xffffffffu, q0, msk);
                s1 += __shfl_xor_sync(0xffffffffu, s1, msk);
                q1 += __shfl_xor_sync(0xffffffffu, q1, msk);
            }
            if (g == 0 && cv) {
                int si = wn + fn * 8 + tq * 2;
                atomicAdd(&s_sum[si], s0);
                atomicAdd(&s_ssq[si], q0);
                atomicAdd(&s_sum[si + 1], s1);
                atomicAdd(&s_ssq[si + 1], q1);
            }
        }
    }
    __syncthreads();
    if (t < 160) {
        int col = n0 + t;
        if (col < DD) {
            atomicAdd(&g_sum[col], s_sum[t]);
            atomicAdd(&g_sumsq[col], s_ssq[t]);
        }
    }
}

// ---------------- BN helpers -------------------------------------------------
__global__ void k_zero_stats() {
    int i = blockIdx.x * blockDim.x + threadIdx.x;
    if (i < DD) { g_sum[i] = 0.f; g_sumsq[i] = 0.f; }
}
__global__ void k_finstats(const float* __restrict__ gam, const float* __restrict__ bet) {
    int c = threadIdx.x;
    if (c < DD) {
        const float invN = 1.f / (float)NN;
        float mean = g_sum[c] * invN;
        float var = g_sumsq[c] * invN - mean * mean;
        float a = rsqrtf(var + BN_EPS) * gam[c];
        g_alpha[c] = a;
        g_beta[c] = bet[c] - mean * a;
    }
}
// P = perm(tf32(relu(C*alpha+beta)))  -- feeds next GEMM
__global__ void k_normA(const float* __restrict__ X, float* __restrict__ P) {
    int t = blockIdx.x * blockDim.x + threadIdx.x;
    if (t >= NN * NGRP) return;
    int n = t / NGRP, gix = t - n * NGRP;
    int k0 = gix * 8;
    const float* xr = X + (size_t)n * DD + k0;
    float* pr = P + (size_t)n * KPAD + k0;
    if (gix < 37) {
        float4 a = *(const float4*)xr;
        float4 b = *(const float4*)(xr + 4);
        float l[8] = {a.x, a.y, a.z, a.w, b.x, b.y, b.z, b.w};
#pragma unroll
        for (int i = 0; i < 8; i++)
            l[i] = to_tf32f(fmaxf(fmaf(l[i], g_alpha[k0 + i], g_beta[k0 + i]), 0.f));
        *(float4*)pr       = make_float4(l[0], l[4], l[1], l[5]);
        *(float4*)(pr + 4) = make_float4(l[2], l[6], l[3], l[7]);
    } else {
        float4 a = *(const float4*)xr;  // logical 296..299
        float l[4] = {a.x, a.y, a.z, a.w};
#pragma unroll
        for (int i = 0; i < 4; i++)
            l[i] = to_tf32f(fmaxf(fmaf(l[i], g_alpha[k0 + i], g_beta[k0 + i]), 0.f));
        *(float4*)pr       = make_float4(l[0], 0.f, l[1], 0.f);
        *(float4*)(pr + 4) = make_float4(l[2], 0.f, l[3], 0.f);
    }
}
// h = relu(C*alpha+beta) (fp32, normal layout)
__global__ void k_normH(const float* __restrict__ X, float* __restrict__ Y) {
    int idx = blockIdx.x * blockDim.x + threadIdx.x;
    if (idx < NN * (DD / 4)) {
        float4 x = ((const float4*)X)[idx];
        int c4 = (idx % (DD / 4)) * 4;
        float4 y;
        y.x = fmaxf(fmaf(x.x, g_alpha[c4],     g_beta[c4]),     0.f);
        y.y = fmaxf(fmaf(x.y, g_alpha[c4 + 1], g_beta[c4 + 1]), 0.f);
        y.z = fmaxf(fmaf(x.z, g_alpha[c4 + 2], g_beta[c4 + 2]), 0.f);
        y.w = fmaxf(fmaf(x.w, g_alpha[c4 + 3], g_beta[c4 + 3]), 0.f);
        ((float4*)Y)[idx] = y;
    }
}

// ---------------- pooling + classifier ---------------------------------------
__global__ void k_bounds(const int* __restrict__ batch) {
    int g = blockIdx.x * blockDim.x + threadIdx.x;
    if (g <= GG) {
        int lo = 0, hi = NN;
        while (lo < hi) {
            int mid = (lo + hi) >> 1;
            if (batch[mid] < g) lo = mid + 1; else hi = mid;
        }
        g_gstart[g] = lo;
    }
}
__global__ void __launch_bounds__(320) k_pool2() {
    int g = blockIdx.x;
    int t = threadIdx.x;
    int s = g_gstart[g], e = g_gstart[g + 1];
    if (t < DD) {
        float acc = 0.f;
        for (int r = s; r < e; r++) acc += g_h[(size_t)r * DD + t];
        float cnt = fmaxf((float)(e - s), 1.f);
        g_pool[g * DD + t] = acc / cnt;
    }
}
__global__ void k_classifier(const float* __restrict__ Wc1, const float* __restrict__ bc1,
                             const float* __restrict__ Wc2, const float* __restrict__ bc2,
                             float* __restrict__ out)
{
    __shared__ float p[DD];
    __shared__ float hid[HH];
    int g = blockIdx.x;
    for (int c = threadIdx.x; c < DD; c += blockDim.x) p[c] = g_pool[g * DD + c];
    __syncthreads();
    int j = threadIdx.x;
    if (j < HH) {
        float s = bc1[j];
        for (int k = 0; k < DD; k++) s = fmaf(p[k], Wc1[k * HH + j], s);
        hid[j] = fmaxf(s, 0.f);
    }
    __syncthreads();
    if (j < NCC) {
        float s = bc2[j];
        for (int k = 0; k < HH; k++) s = fmaf(hid[k], Wc2[k * NCC + j], s);
        out[g * NCC + j] = s;
    }
}

// ---------------- launch -----------------------------------------------------
extern "C" void kernel_launch(void* const* d_in, const int* in_sizes, int n_in,
                              void* d_out, int out_size)
{
    const int*   x  = (const int*)d_in[0];
    const int*   ei = (const int*)d_in[1];
    const float* edge_attr;
    const int*   batch;
    if (in_sizes[2] == EE * EDIMM) {
        edge_attr = (const float*)d_in[2];
        batch     = (const int*)d_in[3];
    } else {
        batch     = (const int*)d_in[2];
        edge_attr = (const float*)d_in[3];
    }
    const float* node_emb = (const float*)d_in[4];
    const float* edge_W   = (const float*)d_in[5];
    const float* edge_b   = (const float*)d_in[6];
    const float* eps      = (const float*)d_in[7];
    const float* W1  = (const float*)d_in[8];
    const float* b1  = (const float*)d_in[9];
    const float* g1  = (const float*)d_in[10];
    const float* be1 = (const float*)d_in[11];
    const float* W2  = (const float*)d_in[12];
    const float* b2  = (const float*)d_in[13];
    const float* g2  = (const float*)d_in[14];
    const float* be2 = (const float*)d_in[15];
    const float* Wc1 = (const float*)d_in[16];
    const float* bc1 = (const float*)d_in[17];
    const float* Wc2 = (const float*)d_in[18];
    const float* bc2 = (const float*)d_in[19];
    float* out = (float*)d_out;

    float *p_h, *p_P, *p_C, *p_Wt;
    cudaGetSymbolAddress((void**)&p_h, g_h);
    cudaGetSymbolAddress((void**)&p_P, g_P);
    cudaGetSymbolAddress((void**)&p_C, g_C);
    cudaGetSymbolAddress((void**)&p_Wt, g_Wt);

    const int ND_BLOCKS = (NN * DD + 255) / 256;
    const int NA_BLOCKS = (NN * NGRP + 255) / 256;
    const int NH_BLOCKS = (NN * (DD / 4) + 255) / 256;

    // CSR build
    k_zero_csr<<<(NN + 256) / 256, 256>>>();
    k_hist<<<(EE + 255) / 256, 256>>>(ei);
    k_scan<<<1, 1024>>>();
    k_scatter<<<(EE + 255) / 256, 256>>>(ei);

    // encoder + weight prep
    k_encode<<<ND_BLOCKS, 256>>>(x, node_emb);
    {
        dim3 tg((KP * KP + 255) / 256, 10);
        k_twist<<<tg, 256>>>(W1, W2);
    }

    dim3 ggrid(2, (NN + 127) / 128);   // (n-tiles, m-tiles)
    for (int l = 0; l < LL; l++) {
        k_aggregate<<<(NN + 3) / 4, 128>>>(edge_attr, edge_W, edge_b, eps, l, p_P);
        k_zero_stats<<<2, 256>>>();
        k_gemm_tc<<<ggrid, 256>>>(p_P, p_Wt + (size_t)l * KP * KP,
                                  b1 + l * DD, p_C, NN);
        k_finstats<<<1, 320>>>(g1 + l * DD, be1 + l * DD);
        k_normA<<<NA_BLOCKS, 256>>>(p_C, p_P);
        k_zero_stats<<<2, 256>>>();
        k_gemm_tc<<<ggrid, 256>>>(p_P, p_Wt + (size_t)(LL + l) * KP * KP,
                                  b2 + l * DD, p_C, NN);
        k_finstats<<<1, 320>>>(g2 + l * DD, be2 + l * DD);
        k_normH<<<NH_BLOCKS, 256>>>(p_C, p_h);
    }

    // pooling + classifier
    k_bounds<<<1, 160>>>(batch);
    k_pool2<<<GG, 320>>>();
    k_classifier<<<GG, 160>>>(Wc1, bc1, Wc2, bc2, out);
}